// round 1
// baseline (speedup 1.0000x reference)
#include <cuda_runtime.h>

#define B 16
#define C 256
#define O_CH 256
#define H 128
#define W 128
#define G 32
#define CG 8    // C/G input channels per group
#define OG 8    // O/G output channels per group
#define HW (H*W)
#define TILE 32
#define TPAD 34

__device__ float d_mean[B*C];
__device__ float d_inv[B*C];
__device__ float d_comb[B*O_CH*CG*9];

// ---------------------------------------------------------------------------
// Kernel 1: per-(b,c) instance-norm statistics over 128x128.
// mean = s/N ; std = sqrt((ss - s*mean)/(N-1)) ; inv = 1/(std + 1e-7)
// ---------------------------------------------------------------------------
__global__ __launch_bounds__(256) void stats_kernel(const float* __restrict__ x) {
    int idx = blockIdx.x;                       // b*C + c
    const float4* p = (const float4*)(x + (size_t)idx * HW);
    float s = 0.f, ss = 0.f;
    for (int i = threadIdx.x; i < HW/4; i += 256) {
        float4 v = p[i];
        s  += v.x + v.y + v.z + v.w;
        ss += v.x*v.x + v.y*v.y + v.z*v.z + v.w*v.w;
    }
    // warp reduce
    #pragma unroll
    for (int o = 16; o > 0; o >>= 1) {
        s  += __shfl_down_sync(0xffffffffu, s,  o);
        ss += __shfl_down_sync(0xffffffffu, ss, o);
    }
    __shared__ float as[8], bs[8];
    int lane = threadIdx.x & 31, wid = threadIdx.x >> 5;
    if (lane == 0) { as[wid] = s; bs[wid] = ss; }
    __syncthreads();
    if (threadIdx.x == 0) {
        float S = 0.f, SS = 0.f;
        #pragma unroll
        for (int w = 0; w < 8; w++) { S += as[w]; SS += bs[w]; }
        float mean = S * (1.0f / HW);
        float var  = (SS - S * mean) * (1.0f / (HW - 1));
        var = fmaxf(var, 0.0f);
        float inv = 1.0f / (sqrtf(var) + 1e-7f);
        d_mean[idx] = mean;
        d_inv[idx]  = inv;
    }
}

// ---------------------------------------------------------------------------
// Kernel 2: fold the grouped 1x1 conv into the 3x3 weights.
// comb[b][o][i][tap] = sum_ip pw[b][o][ip] * dw[b][g*8+ip][i][tap], g = o/8
// ---------------------------------------------------------------------------
__global__ void combine_kernel(const float* __restrict__ dw,
                               const float* __restrict__ pw) {
    int bo = blockIdx.x;          // b*O + o
    int t  = threadIdx.x;         // 0..71 -> i*9 + tap
    int o  = bo % O_CH;
    int b  = bo / O_CH;
    int g  = o >> 3;
    int i  = t / 9, tap = t % 9;
    const float* pwp = pw + (size_t)bo * OG;
    float acc = 0.f;
    #pragma unroll
    for (int ip = 0; ip < 8; ip++) {
        acc += pwp[ip] * dw[(((size_t)b*O_CH + (g*OG + ip))*CG + i)*9 + tap];
    }
    d_comb[(size_t)bo*72 + t] = acc;
}

// ---------------------------------------------------------------------------
// Kernel 3: fused instance-norm + grouped 3x3 conv (8-in -> 8-out) + bias.
// One block = one (b, g, 32x32 tile). 256 threads, 4 pixels x 8 outs each.
// ---------------------------------------------------------------------------
__global__ __launch_bounds__(256) void conv_kernel(const float* __restrict__ x,
                                                   const float* __restrict__ biases,
                                                   float* __restrict__ out) {
    __shared__ float tile[CG][TPAD*TPAD];
    __shared__ float ws[OG*CG*9];
    __shared__ float smean[CG], sinv[CG];

    int b  = blockIdx.z;
    int g  = blockIdx.y;
    int tx = (blockIdx.x & 3) * TILE;
    int ty = (blockIdx.x >> 2) * TILE;
    int tid = threadIdx.x;

    if (tid < CG) {
        smean[tid] = d_mean[b*C + g*CG + tid];
        sinv[tid]  = d_inv [b*C + g*CG + tid];
    }
    __syncthreads();

    // weights for this (b, g): 8 out x 8 in x 9 taps, contiguous
    {
        const float* cb = d_comb + ((size_t)b*O_CH + g*OG) * 72;
        for (int idx = tid; idx < OG*CG*9; idx += 256) ws[idx] = cb[idx];
    }

    // load + normalize 8 input channel tiles with 1-px halo (zero padded)
    {
        const float* xb = x + (size_t)(b*C + g*CG) * HW;
        for (int idx = tid; idx < CG*TPAD*TPAD; idx += 256) {
            int ch = idx / (TPAD*TPAD);
            int rr = idx % (TPAD*TPAD);
            int r  = rr / TPAD, cc = rr % TPAD;
            int gh = ty + r - 1, gw = tx + cc - 1;
            float v = 0.f;
            if ((unsigned)gh < (unsigned)H && (unsigned)gw < (unsigned)W)
                v = (xb[(size_t)ch*HW + gh*W + gw] - smean[ch]) * sinv[ch];
            tile[ch][rr] = v;
        }
    }
    __syncthreads();

    int c  = tid & 31;       // column within tile
    int r0 = tid >> 5;       // 0..7, rows r0 + 8*j

    float acc[OG][4];
    #pragma unroll
    for (int o = 0; o < OG; o++)
        #pragma unroll
        for (int j = 0; j < 4; j++) acc[o][j] = 0.f;

    #pragma unroll 2
    for (int i = 0; i < CG; i++) {
        const float* tp = tile[i];
        #pragma unroll
        for (int kh = 0; kh < 3; kh++) {
            #pragma unroll
            for (int kw = 0; kw < 3; kw++) {
                float v0 = tp[(r0      + kh)*TPAD + c + kw];
                float v1 = tp[(r0 +  8 + kh)*TPAD + c + kw];
                float v2 = tp[(r0 + 16 + kh)*TPAD + c + kw];
                float v3 = tp[(r0 + 24 + kh)*TPAD + c + kw];
                int wbase = i*9 + kh*3 + kw;
                #pragma unroll
                for (int o = 0; o < OG; o++) {
                    float wv = ws[o*72 + wbase];
                    acc[o][0] = fmaf(wv, v0, acc[o][0]);
                    acc[o][1] = fmaf(wv, v1, acc[o][1]);
                    acc[o][2] = fmaf(wv, v2, acc[o][2]);
                    acc[o][3] = fmaf(wv, v3, acc[o][3]);
                }
            }
        }
    }

    float* ob = out + (size_t)(b*O_CH + g*OG) * HW;
    #pragma unroll
    for (int o = 0; o < OG; o++) {
        float bi = biases[b*O_CH + g*OG + o];
        #pragma unroll
        for (int j = 0; j < 4; j++) {
            ob[(size_t)o*HW + (ty + r0 + 8*j)*W + tx + c] = acc[o][j] + bi;
        }
    }
}

// ---------------------------------------------------------------------------
extern "C" void kernel_launch(void* const* d_in, const int* in_sizes, int n_in,
                              void* d_out, int out_size) {
    const float* x      = (const float*)d_in[0];
    const float* dw     = (const float*)d_in[1];
    const float* pw     = (const float*)d_in[2];
    const float* biases = (const float*)d_in[3];
    float* out = (float*)d_out;

    stats_kernel<<<B*C, 256>>>(x);
    combine_kernel<<<B*O_CH, 72>>>(dw, pw);
    conv_kernel<<<dim3(16, G, B), 256>>>(x, biases, out);
}